// round 7
// baseline (speedup 1.0000x reference)
#include <cuda_runtime.h>
#include <cstdint>

#define B_ 4
#define L_ 1024
#define H_ 8
#define E_ 64
#define PLANE (1024*1024)

// Scratch (zero-initialized .bss). Never-written regions (strictly-above-
// diagonal tiles) stay 0 deterministically across graph replays.
__device__ float g_buf1[(size_t)B_*H_*L_*L_];
__device__ float g_buf2[(size_t)B_*H_*L_*L_];
__device__ float g_part[(size_t)B_*H_*L_*32];
__device__ float g_invz[(size_t)B_*H_*L_];

__device__ __forceinline__ uint32_t f2tf32(float x) {
    uint32_t r;
    asm("cvt.rna.tf32.f32 %0, %1;" : "=r"(r) : "f"(x));
    return r;
}

__device__ __forceinline__ void mma_tf32(float c[4],
                                         uint32_t a0, uint32_t a1, uint32_t a2, uint32_t a3,
                                         uint32_t b0, uint32_t b1) {
    asm volatile(
        "mma.sync.aligned.m16n8k8.row.col.f32.tf32.tf32.f32 "
        "{%0,%1,%2,%3}, {%4,%5,%6,%7}, {%8,%9}, {%0,%1,%2,%3};"
        : "+f"(c[0]), "+f"(c[1]), "+f"(c[2]), "+f"(c[3])
        : "r"(a0), "r"(a1), "r"(a2), "r"(a3), "r"(b0), "r"(b1));
}

// ---------------------------------------------------------------------------
// Pass A: S1 = (Q.K^T)*scale via tf32 tensor cores. Causal zeroed in diag
// tiles; fully-masked tiles skipped (.bss zero). grid (16,16,32), block 256.
// ---------------------------------------------------------------------------
__global__ void __launch_bounds__(256) qk_kernel(const float* __restrict__ q,
                                                 const float* __restrict__ k)
{
    const int bh = blockIdx.z;
    const int b  = bh >> 3, h = bh & 7;
    const int l0 = blockIdx.y << 6, s0 = blockIdx.x << 6;
    if (s0 > l0 + 63) return;

    const int tid  = threadIdx.x;
    const int wrp  = tid >> 5, lane = tid & 31;
    const int gid  = lane >> 2, tg = lane & 3;
    const int m0   = (wrp & 3) << 4;
    const int n0   = (wrp >> 2) << 5;

    __shared__ __align__(16) float Qs[64][68];
    __shared__ __align__(16) float Ks[64][68];
    const float* qb = q + (size_t)b * L_ * 512 + h * 64;
    const float* kb = k + (size_t)b * L_ * 512 + h * 64;

    #pragma unroll
    for (int i = 0; i < 4; i++) {
        int row = (tid >> 4) + (i << 4);
        int c   = (tid & 15) << 2;
        *(float4*)&Qs[row][c] = *(const float4*)&qb[(size_t)(l0 + row) * 512 + c];
        *(float4*)&Ks[row][c] = *(const float4*)&kb[(size_t)(s0 + row) * 512 + c];
    }
    __syncthreads();

    float acc[4][4];
    #pragma unroll
    for (int j = 0; j < 4; j++)
        #pragma unroll
        for (int i = 0; i < 4; i++) acc[j][i] = 0.f;

    #pragma unroll
    for (int e0 = 0; e0 < 64; e0 += 8) {
        uint32_t a0 = f2tf32(Qs[m0 + gid][e0 + tg]);
        uint32_t a1 = f2tf32(Qs[m0 + gid + 8][e0 + tg]);
        uint32_t a2 = f2tf32(Qs[m0 + gid][e0 + tg + 4]);
        uint32_t a3 = f2tf32(Qs[m0 + gid + 8][e0 + tg + 4]);
        #pragma unroll
        for (int j = 0; j < 4; j++) {
            int nb = n0 + (j << 3);
            uint32_t b0 = f2tf32(Ks[nb + gid][e0 + tg]);
            uint32_t b1 = f2tf32(Ks[nb + gid][e0 + tg + 4]);
            mma_tf32(acc[j], a0, a1, a2, a3, b0, b1);
        }
    }
    __syncthreads();

    #pragma unroll
    for (int j = 0; j < 4; j++) {
        int nb = n0 + (j << 3) + (tg << 1);
        Qs[m0 + gid][nb]         = acc[j][0];
        Qs[m0 + gid][nb + 1]     = acc[j][1];
        Qs[m0 + gid + 8][nb]     = acc[j][2];
        Qs[m0 + gid + 8][nb + 1] = acc[j][3];
    }
    __syncthreads();

    float* outp = g_buf1 + (size_t)bh * PLANE;
    const float scale = 0.125f;
    #pragma unroll
    for (int i = 0; i < 4; i++) {
        int row = (tid >> 4) + (i << 4);
        int c   = (tid & 15) << 2;
        int l   = l0 + row, sb = s0 + c;
        float4 v = *(const float4*)&Qs[row][c];
        float4 r;
        r.x = (sb + 0 <= l) ? v.x * scale : 0.f;
        r.y = (sb + 1 <= l) ? v.y * scale : 0.f;
        r.z = (sb + 2 <= l) ? v.z * scale : 0.f;
        r.w = (sb + 3 <= l) ? v.w * scale : 0.f;
        *(float4*)&outp[(size_t)l * 1024 + sb] = r;
    }
}

// ---------------------------------------------------------------------------
// Pass B: S2[b,g] = sum_h wpsm[g,h]*conv3x3(S1[b,h]); also emits per-row
// partial sums of exp(S2) (causal-masked) to g_part. grid (32,32,4), block 256.
// ---------------------------------------------------------------------------
__global__ void __launch_bounds__(256) convmix_kernel(const float* __restrict__ mta_k,
                                                      const float* __restrict__ wpsm)
{
    if (blockIdx.x > blockIdx.y) return;
    const int st = blockIdx.x << 5, lt = blockIdx.y << 5, b = blockIdx.z;
    const int tid = threadIdx.x;

    __shared__ __align__(16) float sm[8][34][40];
    __shared__ float kk[8][9];
    __shared__ float wm[8][8];
    if (tid < 72) kk[tid / 9][tid % 9] = mta_k[tid];
    if (tid >= 128 && tid < 192) { int t = tid - 128; wm[t >> 3][t & 7] = wpsm[t]; }

    const float* inb = g_buf1 + (size_t)b * 8 * PLANE;
    for (int idx = tid; idx < 8 * 34 * 10; idx += 256) {
        int h   = idx / 340;
        int rem = idx - h * 340;
        int r   = rem / 10;
        int c4  = rem - r * 10;
        int gl  = lt - 2 + r;
        int gs  = st - 4 + (c4 << 2);
        float4 v = make_float4(0.f, 0.f, 0.f, 0.f);
        if (gl >= 0 && gs >= 0 && gs <= 1020)
            v = *(const float4*)&inb[(size_t)h * PLANE + (size_t)gl * 1024 + gs];
        *(float4*)&sm[h][r][c4 << 2] = v;
    }
    __syncthreads();

    const int li = tid >> 3;
    const int c0 = (tid & 7) << 2;
    const int l  = lt + li;
    const int sq = st + c0;

    float acc[8][4];
    #pragma unroll
    for (int g = 0; g < 8; g++)
        #pragma unroll
        for (int j = 0; j < 4; j++) acc[g][j] = 0.f;

    #pragma unroll 1
    for (int h = 0; h < 8; h++) {
        float cv0 = 0.f, cv1 = 0.f, cv2 = 0.f, cv3 = 0.f;
        #pragma unroll
        for (int i = 0; i < 3; i++) {
            const float* rp = &sm[h][li + i][c0];
            float  a  = rp[3];
            float4 m  = *(const float4*)(rp + 4);
            float2 e2 = *(const float2*)(rp + 8);
            float k0 = kk[h][i*3+0], k1 = kk[h][i*3+1], k2 = kk[h][i*3+2];
            cv0 += k0*a   + k1*m.x + k2*m.y;
            cv1 += k0*m.x + k1*m.y + k2*m.z;
            cv2 += k0*m.y + k1*m.z + k2*m.w;
            cv3 += k0*m.z + k1*m.w + k2*e2.x;
        }
        #pragma unroll
        for (int g = 0; g < 8; g++) {
            float wgh = wm[g][h];
            acc[g][0] += wgh * cv0;
            acc[g][1] += wgh * cv1;
            acc[g][2] += wgh * cv2;
            acc[g][3] += wgh * cv3;
        }
    }

    {
        float* outb = g_buf2 + (size_t)b * 8 * PLANE + (size_t)l * 1024 + sq;
        #pragma unroll
        for (int g = 0; g < 8; g++)
            *(float4*)&outb[(size_t)g * PLANE] =
                make_float4(acc[g][0], acc[g][1], acc[g][2], acc[g][3]);
    }

    const float m0 = (sq + 0 <= l) ? 1.f : 0.f;
    const float m1 = (sq + 1 <= l) ? 1.f : 0.f;
    const float m2 = (sq + 2 <= l) ? 1.f : 0.f;
    const float m3 = (sq + 3 <= l) ? 1.f : 0.f;
    float es[8];
    #pragma unroll
    for (int g = 0; g < 8; g++) {
        es[g] = m0 * __expf(acc[g][0]) + m1 * __expf(acc[g][1])
              + m2 * __expf(acc[g][2]) + m3 * __expf(acc[g][3]);
        #pragma unroll
        for (int o = 1; o < 8; o <<= 1)
            es[g] += __shfl_xor_sync(0xffffffffu, es[g], o);
    }
    const int u = tid & 7;
    float val = es[0];
    val = (u == 1) ? es[1] : val;
    val = (u == 2) ? es[2] : val;
    val = (u == 3) ? es[3] : val;
    val = (u == 4) ? es[4] : val;
    val = (u == 5) ? es[5] : val;
    val = (u == 6) ? es[6] : val;
    val = (u == 7) ? es[7] : val;
    g_part[(((size_t)(b * 8 + u) << 10) + l) * 32 + blockIdx.x] = val;
}

// ---------------------------------------------------------------------------
__global__ void __launch_bounds__(256) invz_kernel()
{
    const int row = blockIdx.x * 256 + threadIdx.x;
    const float* p = g_part + (size_t)row * 32;
    float s = 0.f;
    #pragma unroll
    for (int i = 0; i < 8; i++) {
        float4 v = *(const float4*)&p[i << 2];
        s += v.x + v.y + v.z + v.w;
    }
    g_invz[row] = 1.0f / s;
}

// ---------------------------------------------------------------------------
// FUSED Pass D+E: per (b, head-pair gp, 32-row l-tile). For each 64-col s-tile:
//  1. stage A = exp(S2)*invZ (causal) halo [2][34][72] from buf2
//  2. conv3x3_after + 2x2 head mix + causal zero -> a2 smem [2][32][68]
//  3. tf32 MMA: acc += a2 @ V
// A2 never touches DRAM. grid (32, 16): x = l-tile (reversed, heavy first),
// y = b*4+gp. block 256 (8 warps: warp>>2 = head, 2x2 m/n warp tiles).
// ---------------------------------------------------------------------------
#define RAW_ST 76
#define A2_ST  68
#define VS_ST  68
#define RAW_SZ (2*34*RAW_ST)
#define A2_SZ  (2*32*A2_ST)
#define VS_SZ  (2*64*VS_ST)
#define FUSE_SMEM ((RAW_SZ + A2_SZ + VS_SZ) * sizeof(float))

__global__ void __launch_bounds__(256) av_fused_kernel(const float* __restrict__ v,
                                                       const float* __restrict__ mta_after,
                                                       const float* __restrict__ head_k,
                                                       float* __restrict__ out)
{
    extern __shared__ __align__(16) float smem[];
    float* raw = smem;                 // [2][34][RAW_ST], cols s0-4 .. s0+71
    float* a2  = smem + RAW_SZ;        // [2][32][A2_ST]
    float* vs  = smem + RAW_SZ + A2_SZ;// [2][64][VS_ST]

    const int l0  = (31 - blockIdx.x) << 5;    // heavy blocks first
    const int b   = blockIdx.y >> 2, gp = blockIdx.y & 3;
    const int tid = threadIdx.x;
    const int wrp = tid >> 5, lane = tid & 31;
    const int gid = lane >> 2, tg = lane & 3;
    const int hw  = wrp >> 2;                  // warp's head within pair
    const int m0  = ((wrp >> 1) & 1) << 4;
    const int n0  = (wrp & 1) << 5;

    __shared__ float kk[2][9];
    __shared__ float hk[4];
    if (tid < 18) kk[tid / 9][tid % 9] = mta_after[18 * gp + tid];
    if (tid >= 32 && tid < 36) hk[tid - 32] = head_k[gp * 4 + (tid - 32)];

    const float* s2b = g_buf2 + (size_t)(b * 8 + 2 * gp) * PLANE;
    const float* vb  = v + (size_t)b * L_ * 512 + 2 * gp * 64;

    float acc[4][4];
    #pragma unroll
    for (int j = 0; j < 4; j++)
        #pragma unroll
        for (int i = 0; i < 4; i++) acc[j][i] = 0.f;

    const int n_iter = (l0 >> 6) + 1;
    for (int it = 0; it < n_iter; it++) {
        const int s0 = it << 6;

        // ---- stage exp(S2)*invZ halo: 2 heads x 34 rows x 18 quads ----
        #pragma unroll
        for (int t = 0; t < 5; t++) {
            int idx = tid + t * 256;               // 0..1279; need 1224
            if (idx < 2 * 34 * 18) {
                int h   = idx / (34 * 18);
                int rem = idx - h * (34 * 18);
                int r   = rem / 18;
                int c4  = rem - r * 18;
                int gl  = l0 - 2 + r;
                int gs  = s0 - 4 + (c4 << 2);
                float4 val = make_float4(0.f, 0.f, 0.f, 0.f);
                if (gl >= 0 && gs >= 0 && gs <= 1020) {
                    float4 s2 = *(const float4*)&s2b[(size_t)h * PLANE + (size_t)gl * 1024 + gs];
                    float iz = g_invz[(((size_t)(b * 8 + 2 * gp + h)) << 10) + gl];
                    val.x = (gs + 0 <= gl) ? __expf(s2.x) * iz : 0.f;
                    val.y = (gs + 1 <= gl) ? __expf(s2.y) * iz : 0.f;
                    val.z = (gs + 2 <= gl) ? __expf(s2.z) * iz : 0.f;
                    val.w = (gs + 3 <= gl) ? __expf(s2.w) * iz : 0.f;
                }
                *(float4*)&raw[(h * 34 + r) * RAW_ST + (c4 << 2)] = val;
            }
        }
        // ---- stage V: 2 heads x 64 rows x 16 quads ----
        #pragma unroll
        for (int t = 0; t < 8; t++) {
            int idx = tid + t * 256;               // 0..2047
            int h   = idx >> 10;
            int r   = (idx >> 4) & 63;
            int c   = (idx & 15) << 2;
            float4 vv = *(const float4*)&vb[(size_t)(s0 + r) * 512 + h * 64 + c];
            *(float4*)&vs[(h * 64 + r) * VS_ST + c] = vv;
        }
        __syncthreads();

        // ---- conv both heads + head-pair mix + causal zero -> a2 ----
        {
            float h00 = hk[0], h01 = hk[1], h10 = hk[2], h11 = hk[3];
            #pragma unroll
            for (int t = 0; t < 2; t++) {
                int p  = tid + t * 256;            // 0..511 = 32 rows x 16 quads
                int rr = p >> 4;
                int c0 = (p & 15) << 2;
                int l  = l0 + rr;
                int sq = s0 + c0;
                float c0v[4] = {0.f, 0.f, 0.f, 0.f};
                float c1v[4] = {0.f, 0.f, 0.f, 0.f};
                #pragma unroll
                for (int hh = 0; hh < 2; hh++) {
                    float* cv = hh ? c1v : c0v;
                    #pragma unroll
                    for (int i = 0; i < 3; i++) {
                        const float* rp = &raw[(hh * 34 + rr + i) * RAW_ST + c0];
                        float  a  = rp[3];
                        float4 m  = *(const float4*)(rp + 4);
                        float2 e2 = *(const float2*)(rp + 8);
                        float k0 = kk[hh][i*3+0], k1 = kk[hh][i*3+1], k2 = kk[hh][i*3+2];
                        cv[0] += k0*a   + k1*m.x + k2*m.y;
                        cv[1] += k0*m.x + k1*m.y + k2*m.z;
                        cv[2] += k0*m.y + k1*m.z + k2*m.w;
                        cv[3] += k0*m.z + k1*m.w + k2*e2.x;
                    }
                }
                float cz0 = (sq + 0 <= l) ? 1.f : 0.f;
                float cz1 = (sq + 1 <= l) ? 1.f : 0.f;
                float cz2 = (sq + 2 <= l) ? 1.f : 0.f;
                float cz3 = (sq + 3 <= l) ? 1.f : 0.f;
                *(float4*)&a2[(0 * 32 + rr) * A2_ST + c0] =
                    make_float4((c0v[0]*h00 + c1v[0]*h10) * cz0,
                                (c0v[1]*h00 + c1v[1]*h10) * cz1,
                                (c0v[2]*h00 + c1v[2]*h10) * cz2,
                                (c0v[3]*h00 + c1v[3]*h10) * cz3);
                *(float4*)&a2[(1 * 32 + rr) * A2_ST + c0] =
                    make_float4((c0v[0]*h01 + c1v[0]*h11) * cz0,
                                (c0v[1]*h01 + c1v[1]*h11) * cz1,
                                (c0v[2]*h01 + c1v[2]*h11) * cz2,
                                (c0v[3]*h01 + c1v[3]*h11) * cz3);
            }
        }
        __syncthreads();

        // ---- tf32 MMA: acc += a2[hw] @ vs[hw] ----
        {
            const float* ah = a2 + hw * 32 * A2_ST;
            const float* vh = vs + hw * 64 * VS_ST;
            #pragma unroll
            for (int k0 = 0; k0 < 64; k0 += 8) {
                uint32_t a0 = f2tf32(ah[(m0 + gid) * A2_ST + k0 + tg]);
                uint32_t a1 = f2tf32(ah[(m0 + gid + 8) * A2_ST + k0 + tg]);
                uint32_t a2f = f2tf32(ah[(m0 + gid) * A2_ST + k0 + tg + 4]);
                uint32_t a3 = f2tf32(ah[(m0 + gid + 8) * A2_ST + k0 + tg + 4]);
                #pragma unroll
                for (int j = 0; j < 4; j++) {
                    int nb = n0 + (j << 3);
                    uint32_t b0 = f2tf32(vh[(k0 + tg) * VS_ST + nb + gid]);
                    uint32_t b1 = f2tf32(vh[(k0 + tg + 4) * VS_ST + nb + gid]);
                    mma_tf32(acc[j], a0, a1, a2f, a3, b0, b1);
                }
            }
        }
        __syncthreads();
    }

    // epilogue
    const int hg = 2 * gp + hw;
    #pragma unroll
    for (int j = 0; j < 4; j++) {
        int e  = n0 + (j << 3) + (tg << 1);
        int l1 = l0 + m0 + gid;
        int l2 = l1 + 8;
        *(float2*)&out[((size_t)(b * L_ + l1) * H_ + hg) * E_ + e] =
            make_float2(acc[j][0], acc[j][1]);
        *(float2*)&out[((size_t)(b * L_ + l2) * H_ + hg) * E_ + e] =
            make_float2(acc[j][2], acc[j][3]);
    }
}

// ---------------------------------------------------------------------------
extern "C" void kernel_launch(void* const* d_in, const int* in_sizes, int n_in,
                              void* d_out, int out_size)
{
    const float* q         = (const float*)d_in[0];
    const float* k         = (const float*)d_in[1];
    const float* v         = (const float*)d_in[2];
    const float* mta       = (const float*)d_in[3];
    const float* mta_after = (const float*)d_in[4];
    const float* head_k    = (const float*)d_in[5];
    const float* wpsm      = (const float*)d_in[6];
    float* out = (float*)d_out;

    dim3 gA(16, 16, 32);
    qk_kernel<<<gA, 256>>>(q, k);

    dim3 gB(32, 32, 4);
    convmix_kernel<<<gB, 256>>>(mta, wpsm);

    invz_kernel<<<128, 256>>>();

    cudaFuncSetAttribute(av_fused_kernel, cudaFuncAttributeMaxDynamicSharedMemorySize,
                         (int)FUSE_SMEM);
    dim3 gE(32, 16);
    av_fused_kernel<<<gE, 256, FUSE_SMEM>>>(v, mta_after, head_k, out);
}

// round 8
// speedup vs baseline: 1.4593x; 1.4593x over previous
#include <cuda_runtime.h>
#include <cuda_fp16.h>
#include <cstdint>

#define B_ 4
#define L_ 1024
#define H_ 8
#define E_ 64
#define PLANE (1024*1024)

// fp16 scratch planes (64 MB each, zero-initialized .bss). Never-written
// regions (strictly-above-diagonal tiles) stay 0x0000 = +0.0h deterministically.
__device__ __half g_h1[(size_t)B_*H_*L_*L_];   // S1, then A2
__device__ __half g_h2[(size_t)B_*H_*L_*L_];   // E = exp(S2)
__device__ float  g_part[(size_t)B_*H_*L_*32];
__device__ float  g_invz[(size_t)B_*H_*L_];

__device__ __forceinline__ uint32_t f2tf32(float x) {
    uint32_t r;
    asm("cvt.rna.tf32.f32 %0, %1;" : "=r"(r) : "f"(x));
    return r;
}

__device__ __forceinline__ void mma_tf32(float c[4],
                                         uint32_t a0, uint32_t a1, uint32_t a2, uint32_t a3,
                                         uint32_t b0, uint32_t b1) {
    asm volatile(
        "mma.sync.aligned.m16n8k8.row.col.f32.tf32.tf32.f32 "
        "{%0,%1,%2,%3}, {%4,%5,%6,%7}, {%8,%9}, {%0,%1,%2,%3};"
        : "+f"(c[0]), "+f"(c[1]), "+f"(c[2]), "+f"(c[3])
        : "r"(a0), "r"(a1), "r"(a2), "r"(a3), "r"(b0), "r"(b1));
}

// load 4 consecutive halves -> float4 (8-byte aligned)
__device__ __forceinline__ float4 ldh4(const __half* p) {
    uint2 u = *(const uint2*)p;
    __half2 h0 = *(__half2*)&u.x;
    __half2 h1 = *(__half2*)&u.y;
    float2 f0 = __half22float2(h0);
    float2 f1 = __half22float2(h1);
    return make_float4(f0.x, f0.y, f1.x, f1.y);
}

// store float4 -> 4 consecutive halves
__device__ __forceinline__ void sth4(__half* p, float4 v) {
    __half2 a = __floats2half2_rn(v.x, v.y);
    __half2 b = __floats2half2_rn(v.z, v.w);
    uint2 u;
    u.x = *(uint32_t*)&a;
    u.y = *(uint32_t*)&b;
    *(uint2*)p = u;
}

// ---------------------------------------------------------------------------
// Pass A: S1 = (Q.K^T)*scale via tf32 MMA; causal zeroed; masked tiles skipped.
// Output fp16. grid (16,16,32), block 256.
// ---------------------------------------------------------------------------
__global__ void __launch_bounds__(256) qk_kernel(const float* __restrict__ q,
                                                 const float* __restrict__ k)
{
    const int bh = blockIdx.z;
    const int b  = bh >> 3, h = bh & 7;
    const int l0 = blockIdx.y << 6, s0 = blockIdx.x << 6;
    if (s0 > l0 + 63) return;

    const int tid  = threadIdx.x;
    const int wrp  = tid >> 5, lane = tid & 31;
    const int gid  = lane >> 2, tg = lane & 3;
    const int m0   = (wrp & 3) << 4;
    const int n0   = (wrp >> 2) << 5;

    __shared__ __align__(16) float Qs[64][68];
    __shared__ __align__(16) float Ks[64][68];
    const float* qb = q + (size_t)b * L_ * 512 + h * 64;
    const float* kb = k + (size_t)b * L_ * 512 + h * 64;

    #pragma unroll
    for (int i = 0; i < 4; i++) {
        int row = (tid >> 4) + (i << 4);
        int c   = (tid & 15) << 2;
        *(float4*)&Qs[row][c] = *(const float4*)&qb[(size_t)(l0 + row) * 512 + c];
        *(float4*)&Ks[row][c] = *(const float4*)&kb[(size_t)(s0 + row) * 512 + c];
    }
    __syncthreads();

    float acc[4][4];
    #pragma unroll
    for (int j = 0; j < 4; j++)
        #pragma unroll
        for (int i = 0; i < 4; i++) acc[j][i] = 0.f;

    #pragma unroll
    for (int e0 = 0; e0 < 64; e0 += 8) {
        uint32_t a0 = f2tf32(Qs[m0 + gid][e0 + tg]);
        uint32_t a1 = f2tf32(Qs[m0 + gid + 8][e0 + tg]);
        uint32_t a2 = f2tf32(Qs[m0 + gid][e0 + tg + 4]);
        uint32_t a3 = f2tf32(Qs[m0 + gid + 8][e0 + tg + 4]);
        #pragma unroll
        for (int j = 0; j < 4; j++) {
            int nb = n0 + (j << 3);
            uint32_t b0 = f2tf32(Ks[nb + gid][e0 + tg]);
            uint32_t b1 = f2tf32(Ks[nb + gid][e0 + tg + 4]);
            mma_tf32(acc[j], a0, a1, a2, a3, b0, b1);
        }
    }
    __syncthreads();

    #pragma unroll
    for (int j = 0; j < 4; j++) {
        int nb = n0 + (j << 3) + (tg << 1);
        Qs[m0 + gid][nb]         = acc[j][0];
        Qs[m0 + gid][nb + 1]     = acc[j][1];
        Qs[m0 + gid + 8][nb]     = acc[j][2];
        Qs[m0 + gid + 8][nb + 1] = acc[j][3];
    }
    __syncthreads();

    __half* outp = g_h1 + (size_t)bh * PLANE;
    const float scale = 0.125f;
    #pragma unroll
    for (int i = 0; i < 4; i++) {
        int row = (tid >> 4) + (i << 4);
        int c   = (tid & 15) << 2;
        int l   = l0 + row, sb = s0 + c;
        float4 v = *(const float4*)&Qs[row][c];
        float4 r;
        r.x = (sb + 0 <= l) ? v.x * scale : 0.f;
        r.y = (sb + 1 <= l) ? v.y * scale : 0.f;
        r.z = (sb + 2 <= l) ? v.z * scale : 0.f;
        r.w = (sb + 3 <= l) ? v.w * scale : 0.f;
        sth4(&outp[(size_t)l * 1024 + sb], r);
    }
}

// ---------------------------------------------------------------------------
// Pass B: S2[b,g] = sum_h wpsm[g,h]*conv3x3(S1[b,h]); writes E = exp(S2) (fp16)
// and per-row causal-masked partial sums of exp to g_part.
// grid (32,32,4), block 256, quad per thread.
// ---------------------------------------------------------------------------
__global__ void __launch_bounds__(256) convmix_kernel(const float* __restrict__ mta_k,
                                                      const float* __restrict__ wpsm)
{
    if (blockIdx.x > blockIdx.y) return;
    const int st = blockIdx.x << 5, lt = blockIdx.y << 5, b = blockIdx.z;
    const int tid = threadIdx.x;

    __shared__ __align__(16) float sm[8][34][40];
    __shared__ float kk[8][9];
    __shared__ float wm[8][8];
    if (tid < 72) kk[tid / 9][tid % 9] = mta_k[tid];
    if (tid >= 128 && tid < 192) { int t = tid - 128; wm[t >> 3][t & 7] = wpsm[t]; }

    const __half* inb = g_h1 + (size_t)b * 8 * PLANE;
    for (int idx = tid; idx < 8 * 34 * 10; idx += 256) {
        int h   = idx / 340;
        int rem = idx - h * 340;
        int r   = rem / 10;
        int c4  = rem - r * 10;
        int gl  = lt - 2 + r;
        int gs  = st - 4 + (c4 << 2);
        float4 v = make_float4(0.f, 0.f, 0.f, 0.f);
        if (gl >= 0 && gs >= 0 && gs <= 1020)
            v = ldh4(&inb[(size_t)h * PLANE + (size_t)gl * 1024 + gs]);
        *(float4*)&sm[h][r][c4 << 2] = v;
    }
    __syncthreads();

    const int li = tid >> 3;
    const int c0 = (tid & 7) << 2;
    const int l  = lt + li;
    const int sq = st + c0;

    float acc[8][4];
    #pragma unroll
    for (int g = 0; g < 8; g++)
        #pragma unroll
        for (int j = 0; j < 4; j++) acc[g][j] = 0.f;

    #pragma unroll 1
    for (int h = 0; h < 8; h++) {
        float cv0 = 0.f, cv1 = 0.f, cv2 = 0.f, cv3 = 0.f;
        #pragma unroll
        for (int i = 0; i < 3; i++) {
            const float* rp = &sm[h][li + i][c0];
            float  a  = rp[3];
            float4 m  = *(const float4*)(rp + 4);
            float2 e2 = *(const float2*)(rp + 8);
            float k0 = kk[h][i*3+0], k1 = kk[h][i*3+1], k2 = kk[h][i*3+2];
            cv0 += k0*a   + k1*m.x + k2*m.y;
            cv1 += k0*m.x + k1*m.y + k2*m.z;
            cv2 += k0*m.y + k1*m.z + k2*m.w;
            cv3 += k0*m.z + k1*m.w + k2*e2.x;
        }
        #pragma unroll
        for (int g = 0; g < 8; g++) {
            float wgh = wm[g][h];
            acc[g][0] += wgh * cv0;
            acc[g][1] += wgh * cv1;
            acc[g][2] += wgh * cv2;
            acc[g][3] += wgh * cv3;
        }
    }

    // exp once; store E (fp16) and accumulate masked row partials
    const float m0 = (sq + 0 <= l) ? 1.f : 0.f;
    const float m1 = (sq + 1 <= l) ? 1.f : 0.f;
    const float m2 = (sq + 2 <= l) ? 1.f : 0.f;
    const float m3 = (sq + 3 <= l) ? 1.f : 0.f;

    __half* outb = g_h2 + (size_t)b * 8 * PLANE + (size_t)l * 1024 + sq;
    float es[8];
    #pragma unroll
    for (int g = 0; g < 8; g++) {
        float e0 = __expf(acc[g][0]);
        float e1 = __expf(acc[g][1]);
        float e2v = __expf(acc[g][2]);
        float e3 = __expf(acc[g][3]);
        sth4(&outb[(size_t)g * PLANE], make_float4(e0, e1, e2v, e3));
        es[g] = m0 * e0 + m1 * e1 + m2 * e2v + m3 * e3;
        #pragma unroll
        for (int o = 1; o < 8; o <<= 1)
            es[g] += __shfl_xor_sync(0xffffffffu, es[g], o);
    }
    const int u = tid & 7;
    float val = es[0];
    val = (u == 1) ? es[1] : val;
    val = (u == 2) ? es[2] : val;
    val = (u == 3) ? es[3] : val;
    val = (u == 4) ? es[4] : val;
    val = (u == 5) ? es[5] : val;
    val = (u == 6) ? es[6] : val;
    val = (u == 7) ? es[7] : val;
    g_part[(((size_t)(b * 8 + u) << 10) + l) * 32 + blockIdx.x] = val;
}

// ---------------------------------------------------------------------------
__global__ void __launch_bounds__(256) invz_kernel()
{
    const int row = blockIdx.x * 256 + threadIdx.x;
    const float* p = g_part + (size_t)row * 32;
    float s = 0.f;
    #pragma unroll
    for (int i = 0; i < 8; i++) {
        float4 v = *(const float4*)&p[i << 2];
        s += v.x + v.y + v.z + v.w;
    }
    g_invz[row] = 1.0f / s;
}

// ---------------------------------------------------------------------------
// Pass D (split per head-pair): stages A = E*invZ (causal) for heads 2gp,2gp+1
// (no exp needed — E precomputed); conv3x3_after + 2x2 head mix + causal zero.
// Writes A2 fp16 to g_h1. grid (32,32,16): z = b*4+gp. block 256.
// ---------------------------------------------------------------------------
__global__ void __launch_bounds__(256) convhead_kernel(const float* __restrict__ mta_after,
                                                       const float* __restrict__ head_k)
{
    if (blockIdx.x > blockIdx.y) return;
    const int st = blockIdx.x << 5, lt = blockIdx.y << 5;
    const int b  = blockIdx.z >> 2, gp = blockIdx.z & 3;
    const int tid = threadIdx.x;

    __shared__ __align__(16) float sm[2][34][40];
    __shared__ float kk[2][9];
    __shared__ float hk[4];
    if (tid < 18) kk[tid / 9][tid % 9] = mta_after[18 * gp + tid];
    if (tid >= 32 && tid < 36) hk[tid - 32] = head_k[gp * 4 + (tid - 32)];

    const __half* inb = g_h2 + (size_t)(b * 8 + 2 * gp) * PLANE;
    for (int idx = tid; idx < 2 * 34 * 10; idx += 256) {
        int h   = idx / 340;
        int rem = idx - h * 340;
        int r   = rem / 10;
        int c4  = rem - r * 10;
        int gl  = lt - 2 + r;
        int gs  = st - 4 + (c4 << 2);
        float4 v = make_float4(0.f, 0.f, 0.f, 0.f);
        if (gl >= 0 && gs >= 0 && gs <= 1020) {
            float4 e = ldh4(&inb[(size_t)h * PLANE + (size_t)gl * 1024 + gs]);
            float iz = g_invz[(((size_t)(b * 8 + 2 * gp + h)) << 10) + gl];
            v.x = (gs + 0 <= gl) ? e.x * iz : 0.f;
            v.y = (gs + 1 <= gl) ? e.y * iz : 0.f;
            v.z = (gs + 2 <= gl) ? e.z * iz : 0.f;
            v.w = (gs + 3 <= gl) ? e.w * iz : 0.f;
        }
        *(float4*)&sm[h][r][c4 << 2] = v;
    }
    __syncthreads();

    const int li = tid >> 3;
    const int c0 = (tid & 7) << 2;
    const int l  = lt + li;
    const int sq = st + c0;
    const float cz0 = (sq + 0 <= l) ? 1.f : 0.f;
    const float cz1 = (sq + 1 <= l) ? 1.f : 0.f;
    const float cz2 = (sq + 2 <= l) ? 1.f : 0.f;
    const float cz3 = (sq + 3 <= l) ? 1.f : 0.f;

    float c0v[4] = {0.f, 0.f, 0.f, 0.f};
    float c1v[4] = {0.f, 0.f, 0.f, 0.f};
    #pragma unroll
    for (int hh = 0; hh < 2; hh++) {
        float* cv = hh ? c1v : c0v;
        #pragma unroll
        for (int i = 0; i < 3; i++) {
            const float* rp = &sm[hh][li + i][c0];
            float  a  = rp[3];
            float4 m  = *(const float4*)(rp + 4);
            float2 e2 = *(const float2*)(rp + 8);
            float k0 = kk[hh][i*3+0], k1 = kk[hh][i*3+1], k2 = kk[hh][i*3+2];
            cv[0] += k0*a   + k1*m.x + k2*m.y;
            cv[1] += k0*m.x + k1*m.y + k2*m.z;
            cv[2] += k0*m.y + k1*m.z + k2*m.w;
            cv[3] += k0*m.z + k1*m.w + k2*e2.x;
        }
    }
    float h00 = hk[0], h01 = hk[1], h10 = hk[2], h11 = hk[3];
    __half* outb = g_h1 + (size_t)(b * 8 + 2 * gp) * PLANE + (size_t)l * 1024 + sq;
    sth4(&outb[0],
         make_float4((c0v[0]*h00 + c1v[0]*h10) * cz0,
                     (c0v[1]*h00 + c1v[1]*h10) * cz1,
                     (c0v[2]*h00 + c1v[2]*h10) * cz2,
                     (c0v[3]*h00 + c1v[3]*h10) * cz3));
    sth4(&outb[PLANE],
         make_float4((c0v[0]*h01 + c1v[0]*h11) * cz0,
                     (c0v[1]*h01 + c1v[1]*h11) * cz1,
                     (c0v[2]*h01 + c1v[2]*h11) * cz2,
                     (c0v[3]*h01 + c1v[3]*h11) * cz3));
}

// ---------------------------------------------------------------------------
// Pass E: out = A2 @ V via tf32 MMA. A2 fp16 in g_h1 (above-diag zero).
// Causal k-loop. grid (32,16): x = bh, y reversed (heavy first). block 256.
// ---------------------------------------------------------------------------
__global__ void __launch_bounds__(256) av_kernel(const float* __restrict__ v,
                                                 float* __restrict__ out)
{
    const int bh = blockIdx.x;
    const int b  = bh >> 3, h = bh & 7;
    const int l0 = (15 - blockIdx.y) << 6;
    const int tid = threadIdx.x;
    const int wrp = tid >> 5, lane = tid & 31;
    const int gid = lane >> 2, tg = lane & 3;
    const int m0  = (wrp & 3) << 4;
    const int n0  = (wrp >> 2) << 5;

    __shared__ __align__(16) float As[64][68];
    __shared__ __align__(16) float Vs[64][68];
    const __half* Ab = g_h1 + (size_t)bh * PLANE;
    const float*  vb = v + (size_t)b * L_ * 512 + h * 64;

    float acc[4][4];
    #pragma unroll
    for (int j = 0; j < 4; j++)
        #pragma unroll
        for (int i = 0; i < 4; i++) acc[j][i] = 0.f;

    for (int s0 = 0; s0 <= l0; s0 += 64) {
        #pragma unroll
        for (int i = 0; i < 4; i++) {
            int row = (tid >> 4) + (i << 4);
            int c   = (tid & 15) << 2;
            *(float4*)&As[row][c] = ldh4(&Ab[(size_t)(l0 + row) * 1024 + s0 + c]);
            *(float4*)&Vs[row][c] = *(const float4*)&vb[(size_t)(s0 + row) * 512 + c];
        }
        __syncthreads();

        #pragma unroll
        for (int k0 = 0; k0 < 64; k0 += 8) {
            uint32_t a0 = f2tf32(As[m0 + gid][k0 + tg]);
            uint32_t a1 = f2tf32(As[m0 + gid + 8][k0 + tg]);
            uint32_t a2 = f2tf32(As[m0 + gid][k0 + tg + 4]);
            uint32_t a3 = f2tf32(As[m0 + gid + 8][k0 + tg + 4]);
            #pragma unroll
            for (int j = 0; j < 4; j++) {
                int nb = n0 + (j << 3);
                uint32_t b0 = f2tf32(Vs[k0 + tg][nb + gid]);
                uint32_t b1 = f2tf32(Vs[k0 + tg + 4][nb + gid]);
                mma_tf32(acc[j], a0, a1, a2, a3, b0, b1);
            }
        }
        __syncthreads();
    }

    #pragma unroll
    for (int j = 0; j < 4; j++) {
        int e  = n0 + (j << 3) + (tg << 1);
        int l1 = l0 + m0 + gid;
        int l2 = l1 + 8;
        *(float2*)&out[((size_t)(b * L_ + l1) * H_ + h) * E_ + e] =
            make_float2(acc[j][0], acc[j][1]);
        *(float2*)&out[((size_t)(b * L_ + l2) * H_ + h) * E_ + e] =
            make_float2(acc[j][2], acc[j][3]);
    }
}

// ---------------------------------------------------------------------------
extern "C" void kernel_launch(void* const* d_in, const int* in_sizes, int n_in,
                              void* d_out, int out_size)
{
    const float* q         = (const float*)d_in[0];
    const float* k         = (const float*)d_in[1];
    const float* v         = (const float*)d_in[2];
    const float* mta       = (const float*)d_in[3];
    const float* mta_after = (const float*)d_in[4];
    const float* head_k    = (const float*)d_in[5];
    const float* wpsm      = (const float*)d_in[6];
    float* out = (float*)d_out;

    dim3 gA(16, 16, 32);
    qk_kernel<<<gA, 256>>>(q, k);

    dim3 gB(32, 32, 4);
    convmix_kernel<<<gB, 256>>>(mta, wpsm);

    invz_kernel<<<128, 256>>>();

    dim3 gD(32, 32, 16);
    convhead_kernel<<<gD, 256>>>(mta_after, head_k);

    dim3 gE(32, 16);
    av_kernel<<<gE, 256>>>(v, out);
}

// round 9
// speedup vs baseline: 1.5492x; 1.0615x over previous
#include <cuda_runtime.h>
#include <cuda_fp16.h>
#include <cstdint>

#define B_ 4
#define L_ 1024
#define H_ 8
#define E_ 64
#define PLANE (1024*1024)

// fp16 scratch planes (64 MB each, zero-initialized .bss). Never-written
// regions (strictly-above-diagonal tiles) stay 0x0000 = +0.0h deterministically.
__device__ __half g_h1[(size_t)B_*H_*L_*L_];   // S1, then A2
__device__ __half g_h2[(size_t)B_*H_*L_*L_];   // E = exp(S2)
__device__ float  g_part[(size_t)B_*H_*L_*32];
__device__ float  g_invz[(size_t)B_*H_*L_];

__device__ __forceinline__ void mma_f16(float c[4],
                                        uint32_t a0, uint32_t a1, uint32_t a2, uint32_t a3,
                                        uint32_t b0, uint32_t b1) {
    asm volatile(
        "mma.sync.aligned.m16n8k16.row.col.f32.f16.f16.f32 "
        "{%0,%1,%2,%3}, {%4,%5,%6,%7}, {%8,%9}, {%0,%1,%2,%3};"
        : "+f"(c[0]), "+f"(c[1]), "+f"(c[2]), "+f"(c[3])
        : "r"(a0), "r"(a1), "r"(a2), "r"(a3), "r"(b0), "r"(b1));
}

// load 4 consecutive halves -> float4
__device__ __forceinline__ float4 ldh4(const __half* p) {
    uint2 u = *(const uint2*)p;
    __half2 h0 = *(__half2*)&u.x;
    __half2 h1 = *(__half2*)&u.y;
    float2 f0 = __half22float2(h0);
    float2 f1 = __half22float2(h1);
    return make_float4(f0.x, f0.y, f1.x, f1.y);
}

// store float4 -> 4 consecutive halves
__device__ __forceinline__ void sth4(__half* p, float4 v) {
    __half2 a = __floats2half2_rn(v.x, v.y);
    __half2 b = __floats2half2_rn(v.z, v.w);
    uint2 u;
    u.x = *(uint32_t*)&a;
    u.y = *(uint32_t*)&b;
    *(uint2*)p = u;
}

// ---------------------------------------------------------------------------
// Pass A: S1 = (Q.K^T)*scale via fp16 HMMA (fp32 accum); causal zeroed;
// masked tiles skipped. Output fp16. grid (16,16,32), block 256.
// A frag from Qs[l][e] (row-major), B frag from Ks[s][e] (k-pairs contiguous).
// ---------------------------------------------------------------------------
#define QK_ST 72
__global__ void __launch_bounds__(256) qk_kernel(const float* __restrict__ q,
                                                 const float* __restrict__ k)
{
    const int bh = blockIdx.z;
    const int b  = bh >> 3, h = bh & 7;
    const int l0 = blockIdx.y << 6, s0 = blockIdx.x << 6;
    if (s0 > l0 + 63) return;

    const int tid  = threadIdx.x;
    const int wrp  = tid >> 5, lane = tid & 31;
    const int gid  = lane >> 2, tg = lane & 3;
    const int m0   = (wrp & 3) << 4;
    const int n0   = (wrp >> 2) << 5;

    __shared__ __align__(16) __half Qs[64][QK_ST];
    __shared__ __align__(16) __half Ks[64][QK_ST];
    __shared__ __align__(16) float Cs[64][68];
    const float* qb = q + (size_t)b * L_ * 512 + h * 64;
    const float* kb = k + (size_t)b * L_ * 512 + h * 64;

    #pragma unroll
    for (int i = 0; i < 4; i++) {
        int row = (tid >> 4) + (i << 4);
        int c   = (tid & 15) << 2;
        sth4(&Qs[row][c], *(const float4*)&qb[(size_t)(l0 + row) * 512 + c]);
        sth4(&Ks[row][c], *(const float4*)&kb[(size_t)(s0 + row) * 512 + c]);
    }
    __syncthreads();

    float acc[4][4];
    #pragma unroll
    for (int j = 0; j < 4; j++)
        #pragma unroll
        for (int i = 0; i < 4; i++) acc[j][i] = 0.f;

    #pragma unroll
    for (int e0 = 0; e0 < 64; e0 += 16) {
        uint32_t a0 = *(const uint32_t*)&Qs[m0 + gid][e0 + 2 * tg];
        uint32_t a1 = *(const uint32_t*)&Qs[m0 + gid + 8][e0 + 2 * tg];
        uint32_t a2 = *(const uint32_t*)&Qs[m0 + gid][e0 + 2 * tg + 8];
        uint32_t a3 = *(const uint32_t*)&Qs[m0 + gid + 8][e0 + 2 * tg + 8];
        #pragma unroll
        for (int j = 0; j < 4; j++) {
            int nb = n0 + (j << 3);
            uint32_t b0 = *(const uint32_t*)&Ks[nb + gid][e0 + 2 * tg];
            uint32_t b1 = *(const uint32_t*)&Ks[nb + gid][e0 + 2 * tg + 8];
            mma_f16(acc[j], a0, a1, a2, a3, b0, b1);
        }
    }
    __syncthreads();

    #pragma unroll
    for (int j = 0; j < 4; j++) {
        int nb = n0 + (j << 3) + (tg << 1);
        Cs[m0 + gid][nb]         = acc[j][0];
        Cs[m0 + gid][nb + 1]     = acc[j][1];
        Cs[m0 + gid + 8][nb]     = acc[j][2];
        Cs[m0 + gid + 8][nb + 1] = acc[j][3];
    }
    __syncthreads();

    __half* outp = g_h1 + (size_t)bh * PLANE;
    const float scale = 0.125f;
    #pragma unroll
    for (int i = 0; i < 4; i++) {
        int row = (tid >> 4) + (i << 4);
        int c   = (tid & 15) << 2;
        int l   = l0 + row, sb = s0 + c;
        float4 v = *(const float4*)&Cs[row][c];
        float4 r;
        r.x = (sb + 0 <= l) ? v.x * scale : 0.f;
        r.y = (sb + 1 <= l) ? v.y * scale : 0.f;
        r.z = (sb + 2 <= l) ? v.z * scale : 0.f;
        r.w = (sb + 3 <= l) ? v.w * scale : 0.f;
        sth4(&outp[(size_t)l * 1024 + sb], r);
    }
}

// ---------------------------------------------------------------------------
// Pass B: S2[b,g] = sum_h wpsm[g,h]*conv3x3(S1[b,h]); writes E = exp(S2) (fp16)
// and per-row causal-masked partial sums of exp to g_part.
// grid (32,32,4), block 256, quad per thread.
// ---------------------------------------------------------------------------
__global__ void __launch_bounds__(256) convmix_kernel(const float* __restrict__ mta_k,
                                                      const float* __restrict__ wpsm)
{
    if (blockIdx.x > blockIdx.y) return;
    const int st = blockIdx.x << 5, lt = blockIdx.y << 5, b = blockIdx.z;
    const int tid = threadIdx.x;

    __shared__ __align__(16) float sm[8][34][40];
    __shared__ float kk[8][9];
    __shared__ float wm[8][8];
    if (tid < 72) kk[tid / 9][tid % 9] = mta_k[tid];
    if (tid >= 128 && tid < 192) { int t = tid - 128; wm[t >> 3][t & 7] = wpsm[t]; }

    const __half* inb = g_h1 + (size_t)b * 8 * PLANE;
    for (int idx = tid; idx < 8 * 34 * 10; idx += 256) {
        int h   = idx / 340;
        int rem = idx - h * 340;
        int r   = rem / 10;
        int c4  = rem - r * 10;
        int gl  = lt - 2 + r;
        int gs  = st - 4 + (c4 << 2);
        float4 v = make_float4(0.f, 0.f, 0.f, 0.f);
        if (gl >= 0 && gs >= 0 && gs <= 1020)
            v = ldh4(&inb[(size_t)h * PLANE + (size_t)gl * 1024 + gs]);
        *(float4*)&sm[h][r][c4 << 2] = v;
    }
    __syncthreads();

    const int li = tid >> 3;
    const int c0 = (tid & 7) << 2;
    const int l  = lt + li;
    const int sq = st + c0;

    float acc[8][4];
    #pragma unroll
    for (int g = 0; g < 8; g++)
        #pragma unroll
        for (int j = 0; j < 4; j++) acc[g][j] = 0.f;

    #pragma unroll 1
    for (int h = 0; h < 8; h++) {
        float cv0 = 0.f, cv1 = 0.f, cv2 = 0.f, cv3 = 0.f;
        #pragma unroll
        for (int i = 0; i < 3; i++) {
            const float* rp = &sm[h][li + i][c0];
            float  a  = rp[3];
            float4 m  = *(const float4*)(rp + 4);
            float2 e2 = *(const float2*)(rp + 8);
            float k0 = kk[h][i*3+0], k1 = kk[h][i*3+1], k2 = kk[h][i*3+2];
            cv0 += k0*a   + k1*m.x + k2*m.y;
            cv1 += k0*m.x + k1*m.y + k2*m.z;
            cv2 += k0*m.y + k1*m.z + k2*m.w;
            cv3 += k0*m.z + k1*m.w + k2*e2.x;
        }
        #pragma unroll
        for (int g = 0; g < 8; g++) {
            float wgh = wm[g][h];
            acc[g][0] += wgh * cv0;
            acc[g][1] += wgh * cv1;
            acc[g][2] += wgh * cv2;
            acc[g][3] += wgh * cv3;
        }
    }

    const float m0 = (sq + 0 <= l) ? 1.f : 0.f;
    const float m1 = (sq + 1 <= l) ? 1.f : 0.f;
    const float m2 = (sq + 2 <= l) ? 1.f : 0.f;
    const float m3 = (sq + 3 <= l) ? 1.f : 0.f;

    __half* outb = g_h2 + (size_t)b * 8 * PLANE + (size_t)l * 1024 + sq;
    float es[8];
    #pragma unroll
    for (int g = 0; g < 8; g++) {
        float e0 = __expf(acc[g][0]);
        float e1 = __expf(acc[g][1]);
        float e2v = __expf(acc[g][2]);
        float e3 = __expf(acc[g][3]);
        sth4(&outb[(size_t)g * PLANE], make_float4(e0, e1, e2v, e3));
        es[g] = m0 * e0 + m1 * e1 + m2 * e2v + m3 * e3;
        #pragma unroll
        for (int o = 1; o < 8; o <<= 1)
            es[g] += __shfl_xor_sync(0xffffffffu, es[g], o);
    }
    const int u = tid & 7;
    float val = es[0];
    val = (u == 1) ? es[1] : val;
    val = (u == 2) ? es[2] : val;
    val = (u == 3) ? es[3] : val;
    val = (u == 4) ? es[4] : val;
    val = (u == 5) ? es[5] : val;
    val = (u == 6) ? es[6] : val;
    val = (u == 7) ? es[7] : val;
    g_part[(((size_t)(b * 8 + u) << 10) + l) * 32 + blockIdx.x] = val;
}

// ---------------------------------------------------------------------------
__global__ void __launch_bounds__(256) invz_kernel()
{
    const int row = blockIdx.x * 256 + threadIdx.x;
    const float* p = g_part + (size_t)row * 32;
    float s = 0.f;
    #pragma unroll
    for (int i = 0; i < 8; i++) {
        float4 v = *(const float4*)&p[i << 2];
        s += v.x + v.y + v.z + v.w;
    }
    g_invz[row] = 1.0f / s;
}

// ---------------------------------------------------------------------------
// Pass D (split per head-pair): stages A = E*invZ (causal); conv3x3_after +
// 2x2 head mix + causal zero. Writes A2 fp16. grid (32,32,16), block 256.
// ---------------------------------------------------------------------------
__global__ void __launch_bounds__(256) convhead_kernel(const float* __restrict__ mta_after,
                                                       const float* __restrict__ head_k)
{
    if (blockIdx.x > blockIdx.y) return;
    const int st = blockIdx.x << 5, lt = blockIdx.y << 5;
    const int b  = blockIdx.z >> 2, gp = blockIdx.z & 3;
    const int tid = threadIdx.x;

    __shared__ __align__(16) float sm[2][34][40];
    __shared__ float kk[2][9];
    __shared__ float hk[4];
    if (tid < 18) kk[tid / 9][tid % 9] = mta_after[18 * gp + tid];
    if (tid >= 32 && tid < 36) hk[tid - 32] = head_k[gp * 4 + (tid - 32)];

    const __half* inb = g_h2 + (size_t)(b * 8 + 2 * gp) * PLANE;
    for (int idx = tid; idx < 2 * 34 * 10; idx += 256) {
        int h   = idx / 340;
        int rem = idx - h * 340;
        int r   = rem / 10;
        int c4  = rem - r * 10;
        int gl  = lt - 2 + r;
        int gs  = st - 4 + (c4 << 2);
        float4 v = make_float4(0.f, 0.f, 0.f, 0.f);
        if (gl >= 0 && gs >= 0 && gs <= 1020) {
            float4 e = ldh4(&inb[(size_t)h * PLANE + (size_t)gl * 1024 + gs]);
            float iz = g_invz[(((size_t)(b * 8 + 2 * gp + h)) << 10) + gl];
            v.x = (gs + 0 <= gl) ? e.x * iz : 0.f;
            v.y = (gs + 1 <= gl) ? e.y * iz : 0.f;
            v.z = (gs + 2 <= gl) ? e.z * iz : 0.f;
            v.w = (gs + 3 <= gl) ? e.w * iz : 0.f;
        }
        *(float4*)&sm[h][r][c4 << 2] = v;
    }
    __syncthreads();

    const int li = tid >> 3;
    const int c0 = (tid & 7) << 2;
    const int l  = lt + li;
    const int sq = st + c0;
    const float cz0 = (sq + 0 <= l) ? 1.f : 0.f;
    const float cz1 = (sq + 1 <= l) ? 1.f : 0.f;
    const float cz2 = (sq + 2 <= l) ? 1.f : 0.f;
    const float cz3 = (sq + 3 <= l) ? 1.f : 0.f;

    float c0v[4] = {0.f, 0.f, 0.f, 0.f};
    float c1v[4] = {0.f, 0.f, 0.f, 0.f};
    #pragma unroll
    for (int hh = 0; hh < 2; hh++) {
        float* cv = hh ? c1v : c0v;
        #pragma unroll
        for (int i = 0; i < 3; i++) {
            const float* rp = &sm[hh][li + i][c0];
            float  a  = rp[3];
            float4 m  = *(const float4*)(rp + 4);
            float2 e2 = *(const float2*)(rp + 8);
            float k0 = kk[hh][i*3+0], k1 = kk[hh][i*3+1], k2 = kk[hh][i*3+2];
            cv[0] += k0*a   + k1*m.x + k2*m.y;
            cv[1] += k0*m.x + k1*m.y + k2*m.z;
            cv[2] += k0*m.y + k1*m.z + k2*m.w;
            cv[3] += k0*m.z + k1*m.w + k2*e2.x;
        }
    }
    float h00 = hk[0], h01 = hk[1], h10 = hk[2], h11 = hk[3];
    __half* outb = g_h1 + (size_t)(b * 8 + 2 * gp) * PLANE + (size_t)l * 1024 + sq;
    sth4(&outb[0],
         make_float4((c0v[0]*h00 + c1v[0]*h10) * cz0,
                     (c0v[1]*h00 + c1v[1]*h10) * cz1,
                     (c0v[2]*h00 + c1v[2]*h10) * cz2,
                     (c0v[3]*h00 + c1v[3]*h10) * cz3));
    sth4(&outb[PLANE],
         make_float4((c0v[0]*h01 + c1v[0]*h11) * cz0,
                     (c0v[1]*h01 + c1v[1]*h11) * cz1,
                     (c0v[2]*h01 + c1v[2]*h11) * cz2,
                     (c0v[3]*h01 + c1v[3]*h11) * cz3));
}

// ---------------------------------------------------------------------------
// Pass E: out = A2 @ V via fp16 HMMA (fp32 accum). A2 fp16 staged with raw
// copies; V pre-packed as half2 s-pairs (exact B-fragment layout).
// Causal k-loop. grid (32,16): x = bh, y reversed (heavy first). block 256.
// ---------------------------------------------------------------------------
#define AV_AST 72
__global__ void __launch_bounds__(256) av_kernel(const float* __restrict__ v,
                                                 float* __restrict__ out)
{
    const int bh = blockIdx.x;
    const int b  = bh >> 3, h = bh & 7;
    const int l0 = (15 - blockIdx.y) << 6;
    const int tid = threadIdx.x;
    const int wrp = tid >> 5, lane = tid & 31;
    const int gid = lane >> 2, tg = lane & 3;
    const int m0  = (wrp & 3) << 4;
    const int n0  = (wrp >> 2) << 5;

    __shared__ __align__(16) __half   As[64][AV_AST];  // [l][s]
    __shared__ __align__(16) __half2  Vp[64][33];      // [e][s2] = {V[2s2][e],V[2s2+1][e]}
    const __half* Ab = g_h1 + (size_t)bh * PLANE;
    const float*  vb = v + (size_t)b * L_ * 512 + h * 64;

    float acc[4][4];
    #pragma unroll
    for (int j = 0; j < 4; j++)
        #pragma unroll
        for (int i = 0; i < 4; i++) acc[j][i] = 0.f;

    for (int s0 = 0; s0 <= l0; s0 += 64) {
        // A2: raw fp16 copy, [l][s]
        #pragma unroll
        for (int i = 0; i < 4; i++) {
            int row = (tid >> 4) + (i << 4);
            int c   = (tid & 15) << 2;
            *(uint2*)&As[row][c] = *(const uint2*)&Ab[(size_t)(l0 + row) * 1024 + s0 + c];
        }
        // V: pack s-pairs into half2 at [e][s2]
        #pragma unroll
        for (int t = 0; t < 2; t++) {
            int idx = tid + (t << 8);          // 0..511 = 32 s2 x 16 quads
            int s2  = idx >> 4;
            int e   = (idx & 15) << 2;
            float4 va = *(const float4*)&vb[(size_t)(s0 + 2 * s2) * 512 + e];
            float4 vc = *(const float4*)&vb[(size_t)(s0 + 2 * s2 + 1) * 512 + e];
            Vp[e + 0][s2] = __floats2half2_rn(va.x, vc.x);
            Vp[e + 1][s2] = __floats2half2_rn(va.y, vc.y);
            Vp[e + 2][s2] = __floats2half2_rn(va.z, vc.z);
            Vp[e + 3][s2] = __floats2half2_rn(va.w, vc.w);
        }
        __syncthreads();

        #pragma unroll
        for (int k0 = 0; k0 < 64; k0 += 16) {
            uint32_t a0 = *(const uint32_t*)&As[m0 + gid][k0 + 2 * tg];
            uint32_t a1 = *(const uint32_t*)&As[m0 + gid + 8][k0 + 2 * tg];
            uint32_t a2 = *(const uint32_t*)&As[m0 + gid][k0 + 2 * tg + 8];
            uint32_t a3 = *(const uint32_t*)&As[m0 + gid + 8][k0 + 2 * tg + 8];
            int sp = k0 >> 1;
            #pragma unroll
            for (int j = 0; j < 4; j++) {
                int nb = n0 + (j << 3);
                uint32_t b0 = *(const uint32_t*)&Vp[nb + gid][sp + tg];
                uint32_t b1 = *(const uint32_t*)&Vp[nb + gid][sp + tg + 4];
                mma_f16(acc[j], a0, a1, a2, a3, b0, b1);
            }
        }
        __syncthreads();
    }

    #pragma unroll
    for (int j = 0; j < 4; j++) {
        int e  = n0 + (j << 3) + (tg << 1);
        int l1 = l0 + m0 + gid;
        int l2 = l1 + 8;
        *(float2*)&out[((size_t)(b * L_ + l1) * H_ + h) * E_ + e] =
            make_float2(acc[j][0], acc[j][1]);
        *(float2*)&out[((size_t)(b * L_ + l2) * H_ + h) * E_ + e] =
            make_float2(acc[j][2], acc[j][3]);
    }
}

// ---------------------------------------------------------------------------
extern "C" void kernel_launch(void* const* d_in, const int* in_sizes, int n_in,
                              void* d_out, int out_size)
{
    const float* q         = (const float*)d_in[0];
    const float* k         = (const float*)d_in[1];
    const float* v         = (const float*)d_in[2];
    const float* mta       = (const float*)d_in[3];
    const float* mta_after = (const float*)d_in[4];
    const float* head_k    = (const float*)d_in[5];
    const float* wpsm      = (const float*)d_in[6];
    float* out = (float*)d_out;

    dim3 gA(16, 16, 32);
    qk_kernel<<<gA, 256>>>(q, k);

    dim3 gB(32, 32, 4);
    convmix_kernel<<<gB, 256>>>(mta, wpsm);

    invz_kernel<<<128, 256>>>();

    dim3 gD(32, 32, 16);
    convhead_kernel<<<gD, 256>>>(mta_after, head_k);

    dim3 gE(32, 16);
    av_kernel<<<gE, 256>>>(v, out);
}